// round 2
// baseline (speedup 1.0000x reference)
#include <cuda_runtime.h>
#include <cuda_bf16.h>
#include <math.h>

// ---------------- problem constants ----------------
#define BATCH   8192
#define D_IN    128
#define D_COND  3
#define HID     1024
#define NLAY    4
#define NQ      8
#define KCB     1024           // codebook size
#define H3      (3*HID)        // 3072
#define DECK    (HID + D_IN)   // 1152
#define LPN     512
#define INV_TAU (1.0f/0.6f)

// ---------------- scratch (no allocation allowed) ----------------
__device__ float g_h_in  [(size_t)BATCH * HID];    // input-projection output
__device__ float g_gi    [(size_t)BATCH * H3];     // x @ W_ih^T
__device__ float g_gh    [(size_t)BATCH * H3];     // h @ W_hh^T
__device__ float g_dec_in[(size_t)BATCH * DECK];   // [h_out | cum]

// =====================================================================
// Generic SGEMM: C[M,N] = A[M,K] @ W[N,K]^T + bias[N]
// BM=BN=128, BK=8, 256 threads, 8x8 per-thread microtile.
// AVEC: whether A rows are 16B-alignable (lda % 4 == 0).
// =====================================================================
template <bool AVEC>
__global__ void __launch_bounds__(256)
sgemm_bias(const float* __restrict__ A, int lda,
           const float* __restrict__ W, int ldw,
           const float* __restrict__ bias,
           float* __restrict__ C, int ldc, int K)
{
    __shared__ float As[8][128];
    __shared__ float Bs[8][128];

    const int tid  = threadIdx.x;
    const int bm   = blockIdx.y * 128;
    const int bn   = blockIdx.x * 128;
    const int tRow = (tid >> 4) * 8;       // 0..120
    const int tCol = (tid & 15) * 8;       // 0..120
    const int lRow = tid >> 1;             // 0..127
    const int lCol = (tid & 1) * 4;        // 0 or 4

    const float* Aptr = A + (size_t)(bm + lRow) * lda + lCol;
    const float* Wptr = W + (size_t)(bn + lRow) * ldw + lCol;

    float acc[8][8];
#pragma unroll
    for (int i = 0; i < 8; i++)
#pragma unroll
        for (int j = 0; j < 8; j++) acc[i][j] = 0.f;

    for (int k0 = 0; k0 < K; k0 += 8) {
        float4 av;
        if (AVEC) {
            av = *(const float4*)(Aptr + k0);
        } else {
            av.x = Aptr[k0 + 0]; av.y = Aptr[k0 + 1];
            av.z = Aptr[k0 + 2]; av.w = Aptr[k0 + 3];
        }
        float4 wv = *(const float4*)(Wptr + k0);

        As[lCol + 0][lRow] = av.x; As[lCol + 1][lRow] = av.y;
        As[lCol + 2][lRow] = av.z; As[lCol + 3][lRow] = av.w;
        Bs[lCol + 0][lRow] = wv.x; Bs[lCol + 1][lRow] = wv.y;
        Bs[lCol + 2][lRow] = wv.z; Bs[lCol + 3][lRow] = wv.w;
        __syncthreads();

#pragma unroll
        for (int kk = 0; kk < 8; kk++) {
            float ra[8], rb[8];
#pragma unroll
            for (int i = 0; i < 8; i++) ra[i] = As[kk][tRow + i];
#pragma unroll
            for (int j = 0; j < 8; j++) rb[j] = Bs[kk][tCol + j];
#pragma unroll
            for (int i = 0; i < 8; i++)
#pragma unroll
                for (int j = 0; j < 8; j++)
                    acc[i][j] = fmaf(ra[i], rb[j], acc[i][j]);
        }
        __syncthreads();
    }

#pragma unroll
    for (int i = 0; i < 8; i++) {
        float* Crow = C + (size_t)(bm + tRow + i) * ldc + bn + tCol;
#pragma unroll
        for (int j = 0; j < 8; j++)
            Crow[j] = acc[i][j] + bias[bn + tCol + j];
    }
}

// =====================================================================
// cond projection: h_in[b, 512+n] = x[b,128:131] . cond_w[n,:] + cond_b[n]
// =====================================================================
__global__ void cond_proj(const float* __restrict__ x,
                          const float* __restrict__ cw,
                          const float* __restrict__ cb,
                          float* __restrict__ h_in)
{
    int idx = blockIdx.x * blockDim.x + threadIdx.x;   // BATCH*512
    int b = idx >> 9, n = idx & 511;
    const float* xr = x + (size_t)b * (D_IN + D_COND) + D_IN;
    float v = cb[n] + xr[0] * cw[n*3+0] + xr[1] * cw[n*3+1] + xr[2] * cw[n*3+2];
    h_in[(size_t)b * HID + LPN + n] = v;
}

// =====================================================================
// GRU gates (torch r,z,n convention)
// =====================================================================
__device__ __forceinline__ float sigm(float v) { return 1.f / (1.f + expf(-v)); }

__global__ void gru_gate(const float* __restrict__ gi,
                         const float* __restrict__ gh,
                         const float* __restrict__ hprev,
                         float* __restrict__ hout,
                         float* __restrict__ dec_in, int writeDec)
{
    int idx = blockIdx.x * blockDim.x + threadIdx.x;   // BATCH*HID
    int b = idx >> 10, j = idx & 1023;
    const float* gib = gi + (size_t)b * H3;
    const float* ghb = gh + (size_t)b * H3;
    float r = sigm(gib[j]        + ghb[j]);
    float z = sigm(gib[HID + j]  + ghb[HID + j]);
    float n = tanhf(gib[2*HID+j] + r * ghb[2*HID+j]);
    float hp = hprev[idx];
    float h  = (1.f - z) * n + z * hp;
    hout[idx] = h;
    if (writeDec) dec_in[(size_t)b * DECK + j] = h;
}

// =====================================================================
// zero the cum-slice of dec_in (must happen every call: graph replays)
// =====================================================================
__global__ void zero_tail(float* __restrict__ dec_in)
{
    int idx = blockIdx.x * blockDim.x + threadIdx.x;   // BATCH*D_IN
    int b = idx >> 7, j = idx & 127;
    dec_in[(size_t)b * DECK + HID + j] = 0.f;
}

// =====================================================================
// Fused per-q RVQ step: softmax(logits/tau) -> e = w @ E ; cum += e ; step += e
// 8 batch rows per block (one warp per row for softmax), 256 threads.
// =====================================================================
__global__ void __launch_bounds__(256)
rvq_step(const float* __restrict__ logits,   // (BATCH, KCB) for this q
         const float* __restrict__ E,        // (KCB, D_IN)  for this q
         float* __restrict__ dec_in,         // (BATCH, DECK)
         float* __restrict__ step_out,       // (BATCH, D_IN)
         int q)
{
    __shared__ float sw[8][KCB];
    __shared__ float ssum[8];

    const int tid  = threadIdx.x;
    const int warp = tid >> 5, lane = tid & 31;
    const size_t rowBase = (size_t)blockIdx.x * 8;

    // ---- phase 1: one warp per row, unnormalized softmax into smem ----
    {
        const float* lr = logits + (rowBase + warp) * KCB;
        float v[32];
        float vmax = -INFINITY;
#pragma unroll
        for (int i = 0; i < 32; i++) {
            v[i] = lr[lane + 32*i];
            vmax = fmaxf(vmax, v[i]);
        }
#pragma unroll
        for (int o = 16; o; o >>= 1) vmax = fmaxf(vmax, __shfl_xor_sync(0xffffffffu, vmax, o));
        float s = 0.f;
#pragma unroll
        for (int i = 0; i < 32; i++) {
            float e = expf((v[i] - vmax) * INV_TAU);
            sw[warp][lane + 32*i] = e;
            s += e;
        }
#pragma unroll
        for (int o = 16; o; o >>= 1) s += __shfl_xor_sync(0xffffffffu, s, o);
        if (lane == 0) ssum[warp] = s;
    }
    __syncthreads();

    // ---- phase 2: e[r][j] = sum_k w[r][k] * E[k][j], 4 rows per thread ----
    const int j     = tid & 127;
    const int rbase = tid >> 7;     // 0 or 1
    float acc[4] = {0.f, 0.f, 0.f, 0.f};
    for (int k = 0; k < KCB; k++) {
        float ev = E[(size_t)k * D_IN + j];
#pragma unroll
        for (int r = 0; r < 4; r++)
            acc[r] = fmaf(sw[rbase + 2*r][k], ev, acc[r]);
    }
#pragma unroll
    for (int r = 0; r < 4; r++) {
        int rr = rbase + 2*r;
        float e = acc[r] / ssum[rr];
        size_t b = rowBase + rr;
        float prev = (q == 0) ? 0.f : step_out[b * D_IN + j];   // d_out is poisoned: write on q==0
        step_out[b * D_IN + j] = prev + e;
        if (q < NQ - 1)
            dec_in[b * DECK + HID + j] += e;    // tail pre-zeroed by zero_tail
    }
}

// =====================================================================
extern "C" void kernel_launch(void* const* d_in, const int* in_sizes, int n_in,
                              void* d_out, int out_size)
{
    const float* x      = (const float*)d_in[0];
    const float* hidden = (const float*)d_in[1];
    const float* lat_w  = (const float*)d_in[2];
    const float* lat_b  = (const float*)d_in[3];
    const float* cond_w = (const float*)d_in[4];
    const float* cond_b = (const float*)d_in[5];
    const float* gwih   = (const float*)d_in[6];
    const float* gwhh   = (const float*)d_in[7];
    const float* gbih   = (const float*)d_in[8];
    const float* gbhh   = (const float*)d_in[9];
    const float* dec_w  = (const float*)d_in[10];
    const float* dec_b  = (const float*)d_in[11];
    const float* E_eff  = (const float*)d_in[12];

    const size_t BH = (size_t)BATCH * HID;
    const size_t BK = (size_t)BATCH * KCB;

    float* out_logits = (float*)d_out;                       // (NQ, B, K)
    float* out_hidden = out_logits + (size_t)NQ * BK;        // (L, B, H)
    float* out_step   = out_hidden + (size_t)NLAY * BH;      // (B, D_IN)

    float *h_in, *gi, *gh, *dec_in;
    cudaGetSymbolAddress((void**)&h_in,   g_h_in);
    cudaGetSymbolAddress((void**)&gi,     g_gi);
    cudaGetSymbolAddress((void**)&gh,     g_gh);
    cudaGetSymbolAddress((void**)&dec_in, g_dec_in);

    // ---- input projections: h_in = [x[:, :128] @ lat_w^T + b | cond] ----
    sgemm_bias<false><<<dim3(LPN/128, BATCH/128), 256>>>(
        x, D_IN + D_COND, lat_w, D_IN, lat_b, h_in, HID, D_IN);
    cond_proj<<<(BATCH*512)/256, 256>>>(x, cond_w, cond_b, h_in);

    // ---- 4-layer GRU (single timestep) ----
    for (int l = 0; l < NLAY; l++) {
        const float* xl = (l == 0) ? h_in : (out_hidden + (size_t)(l-1) * BH);
        sgemm_bias<true><<<dim3(H3/128, BATCH/128), 256>>>(
            xl, HID, gwih + (size_t)l * H3 * HID, HID,
            gbih + (size_t)l * H3, gi, H3, HID);
        sgemm_bias<true><<<dim3(H3/128, BATCH/128), 256>>>(
            hidden + (size_t)l * BH, HID, gwhh + (size_t)l * H3 * HID, HID,
            gbhh + (size_t)l * H3, gh, H3, HID);
        gru_gate<<<(int)(BH/256), 256>>>(
            gi, gh, hidden + (size_t)l * BH,
            out_hidden + (size_t)l * BH, dec_in, (l == NLAY-1) ? 1 : 0);
    }

    // ---- RVQ cascade ----
    zero_tail<<<(BATCH*D_IN)/256, 256>>>(dec_in);
    for (int q = 0; q < NQ; q++) {
        sgemm_bias<true><<<dim3(KCB/128, BATCH/128), 256>>>(
            dec_in, DECK, dec_w + (size_t)q * KCB * DECK, DECK,
            dec_b + (size_t)q * KCB, out_logits + (size_t)q * BK, KCB, DECK);
        rvq_step<<<BATCH/8, 256>>>(
            out_logits + (size_t)q * BK, E_eff + (size_t)q * KCB * D_IN,
            dec_in, out_step, q);
    }
}

// round 4
// speedup vs baseline: 3.3809x; 3.3809x over previous
#include <cuda_runtime.h>
#include <cuda_bf16.h>
#include <math.h>
#include <stdint.h>

// ---------------- problem constants ----------------
#define BATCH   8192
#define D_IN    128
#define D_COND  3
#define HID     1024
#define NLAY    4
#define NQ      8
#define KCB     1024
#define H3      (3*HID)        // 3072
#define DECK    (HID + D_IN)   // 1152
#define LPN     512
#define INV_TAU (1.0f/0.6f)

// ---------------- scratch (no allocation allowed) ----------------
__device__ float g_h_in  [(size_t)BATCH * HID];
__device__ float g_gi    [(size_t)BATCH * H3];
__device__ float g_gh    [(size_t)BATCH * H3];
__device__ float g_dec_in[(size_t)BATCH * DECK];
__device__ float g_w     [(size_t)BATCH * KCB];     // softmax weights
__device__ float g_e     [(size_t)BATCH * D_IN];    // e_q
__device__ float g_ET    [(size_t)NQ * D_IN * KCB]; // E transposed
__device__ float g_zero  [1024];                    // stays 0 (never written)

// =====================================================================
// tf32 mma.sync GEMM:  C[M,N] = A[M,K] @ W[N,K]^T + bias[N]
//   BM=128, BN=128, BK=32, 256 threads (8 warps, 2m x 4n),
//   warp tile 64x32 (4x4 of m16n8k8), cp.async double buffer.
//   Requires: lda/ldw % 4 == 0, K % 32 == 0, M % 128 == 0, N % 128 == 0.
// =====================================================================
#define SPAD 36                          // padded row stride (floats)
#define STAGE_F (128 * SPAD)             // floats per operand per stage

__device__ __forceinline__ uint32_t f2tf32(float f) {
    uint32_t u;
    asm("cvt.rna.tf32.f32 %0, %1;" : "=r"(u) : "f"(f));
    return u;
}

__device__ __forceinline__ void mma_tf32(float* c, const uint32_t* a, const uint32_t* b) {
    asm volatile(
        "mma.sync.aligned.m16n8k8.row.col.f32.tf32.tf32.f32 "
        "{%0,%1,%2,%3}, {%4,%5,%6,%7}, {%8,%9}, {%0,%1,%2,%3};"
        : "+f"(c[0]), "+f"(c[1]), "+f"(c[2]), "+f"(c[3])
        : "r"(a[0]), "r"(a[1]), "r"(a[2]), "r"(a[3]), "r"(b[0]), "r"(b[1]));
}

__device__ __forceinline__ uint32_t smem_u32(const void* p) {
    uint32_t a;
    asm("{ .reg .u64 t; cvta.to.shared.u64 t, %1; cvt.u32.u64 %0, t; }" : "=r"(a) : "l"(p));
    return a;
}
#define CP_ASYNC16(dst, src) \
    asm volatile("cp.async.cg.shared.global [%0], [%1], 16;" :: "r"(dst), "l"(src) : "memory")
#define CP_COMMIT() asm volatile("cp.async.commit_group;" ::: "memory")
template <int N> __device__ __forceinline__ void cp_wait() {
    asm volatile("cp.async.wait_group %0;" :: "n"(N) : "memory");
}

__global__ void __launch_bounds__(256, 2)
mma_gemm(const float* __restrict__ A, int lda,
         const float* __restrict__ W, int ldw,
         const float* __restrict__ bias,
         float* __restrict__ C, int ldc, int K)
{
    extern __shared__ float smem[];
    float* As = smem;                       // [2][128][SPAD]
    float* Bs = smem + 2 * STAGE_F;         // [2][128][SPAD]

    const int tid  = threadIdx.x;
    const int lane = tid & 31, wid = tid >> 5;
    const int bm = blockIdx.y * 128, bn = blockIdx.x * 128;
    const int wm = (wid >> 2) << 6;         // 0 / 64
    const int wn = (wid & 3) << 5;          // 0 / 32 / 64 / 96

    // loader indexing: 256 thr; each does 4 rows x 1 float4 per operand
    const int lrow = tid >> 3;              // 0..31
    const int lq   = tid & 7;               // 0..7 (float4 within 32-float row)
    const uint32_t sA = smem_u32(As);
    const uint32_t sB = smem_u32(Bs);

    float acc[4][4][4];
#pragma unroll
    for (int i = 0; i < 4; i++)
#pragma unroll
        for (int j = 0; j < 4; j++)
#pragma unroll
            for (int k = 0; k < 4; k++) acc[i][j][k] = 0.f;

    const int nK = K / 32;

    auto prefetch = [&](int kt, int s) {
        const float* Ab = A + (size_t)(bm + lrow) * lda + kt * 32 + lq * 4;
        const float* Wb = W + (size_t)(bn + lrow) * ldw + kt * 32 + lq * 4;
        uint32_t dA = sA + (s * STAGE_F + lrow * SPAD + lq * 4) * 4;
        uint32_t dB = sB + (s * STAGE_F + lrow * SPAD + lq * 4) * 4;
#pragma unroll
        for (int i = 0; i < 4; i++) {
            CP_ASYNC16(dA + i * 32 * SPAD * 4, Ab + (size_t)(i * 32) * lda);
            CP_ASYNC16(dB + i * 32 * SPAD * 4, Wb + (size_t)(i * 32) * ldw);
        }
        CP_COMMIT();
    };

    prefetch(0, 0);

    for (int kt = 0; kt < nK; kt++) {
        if (kt + 1 < nK) {
            prefetch(kt + 1, (kt + 1) & 1);
            cp_wait<1>();
        } else {
            cp_wait<0>();
        }
        __syncthreads();

        const float* Ac = As + (kt & 1) * STAGE_F;
        const float* Bc = Bs + (kt & 1) * STAGE_F;
#pragma unroll
        for (int k8 = 0; k8 < 4; k8++) {
            const int kc = k8 * 8 + (lane & 3);
            uint32_t a[4][4], b[4][2];
#pragma unroll
            for (int mt = 0; mt < 4; mt++) {
                const float* ar = Ac + (wm + mt * 16 + (lane >> 2)) * SPAD;
                a[mt][0] = f2tf32(ar[kc]);
                a[mt][1] = f2tf32(ar[8 * SPAD + kc]);
                a[mt][2] = f2tf32(ar[kc + 4]);
                a[mt][3] = f2tf32(ar[8 * SPAD + kc + 4]);
            }
#pragma unroll
            for (int nt = 0; nt < 4; nt++) {
                const float* br = Bc + (wn + nt * 8 + (lane >> 2)) * SPAD;
                b[nt][0] = f2tf32(br[kc]);
                b[nt][1] = f2tf32(br[kc + 4]);
            }
#pragma unroll
            for (int mt = 0; mt < 4; mt++)
#pragma unroll
                for (int nt = 0; nt < 4; nt++)
                    mma_tf32(acc[mt][nt], a[mt], b[nt]);
        }
        __syncthreads();
    }

    // ---- epilogue ----
#pragma unroll
    for (int mt = 0; mt < 4; mt++) {
        const int r0 = bm + wm + mt * 16 + (lane >> 2);
#pragma unroll
        for (int nt = 0; nt < 4; nt++) {
            const int c0 = bn + wn + nt * 8 + (lane & 3) * 2;
            const float b0 = bias[c0], b1 = bias[c0 + 1];
            float2 v0 = make_float2(acc[mt][nt][0] + b0, acc[mt][nt][1] + b1);
            float2 v1 = make_float2(acc[mt][nt][2] + b0, acc[mt][nt][3] + b1);
            *(float2*)(C + (size_t)r0 * ldc + c0) = v0;
            *(float2*)(C + (size_t)(r0 + 8) * ldc + c0) = v1;
        }
    }
}

// =====================================================================
// fp32 SGEMM kept only for the tiny latent projection (lda=131, unaligned)
// =====================================================================
__global__ void __launch_bounds__(256)
sgemm_lat(const float* __restrict__ A, int lda,
          const float* __restrict__ W, int ldw,
          const float* __restrict__ bias,
          float* __restrict__ C, int ldc, int K)
{
    __shared__ float As[8][128];
    __shared__ float Bs[8][128];
    const int tid = threadIdx.x;
    const int bm = blockIdx.y * 128, bn = blockIdx.x * 128;
    const int tRow = (tid >> 4) * 8, tCol = (tid & 15) * 8;
    const int lRow = tid >> 1, lCol = (tid & 1) * 4;
    const float* Aptr = A + (size_t)(bm + lRow) * lda + lCol;
    const float* Wptr = W + (size_t)(bn + lRow) * ldw + lCol;
    float acc[8][8];
#pragma unroll
    for (int i = 0; i < 8; i++)
#pragma unroll
        for (int j = 0; j < 8; j++) acc[i][j] = 0.f;
    for (int k0 = 0; k0 < K; k0 += 8) {
        float4 av;
        av.x = Aptr[k0]; av.y = Aptr[k0+1]; av.z = Aptr[k0+2]; av.w = Aptr[k0+3];
        float4 wv = *(const float4*)(Wptr + k0);
        As[lCol+0][lRow]=av.x; As[lCol+1][lRow]=av.y; As[lCol+2][lRow]=av.z; As[lCol+3][lRow]=av.w;
        Bs[lCol+0][lRow]=wv.x; Bs[lCol+1][lRow]=wv.y; Bs[lCol+2][lRow]=wv.z; Bs[lCol+3][lRow]=wv.w;
        __syncthreads();
#pragma unroll
        for (int kk = 0; kk < 8; kk++) {
            float ra[8], rb[8];
#pragma unroll
            for (int i = 0; i < 8; i++) ra[i] = As[kk][tRow+i];
#pragma unroll
            for (int j = 0; j < 8; j++) rb[j] = Bs[kk][tCol+j];
#pragma unroll
            for (int i = 0; i < 8; i++)
#pragma unroll
                for (int j = 0; j < 8; j++) acc[i][j] = fmaf(ra[i], rb[j], acc[i][j]);
        }
        __syncthreads();
    }
#pragma unroll
    for (int i = 0; i < 8; i++) {
        float* Crow = C + (size_t)(bm + tRow + i) * ldc + bn + tCol;
#pragma unroll
        for (int j = 0; j < 8; j++) Crow[j] = acc[i][j] + bias[bn + tCol + j];
    }
}

// =====================================================================
__global__ void cond_proj(const float* __restrict__ x,
                          const float* __restrict__ cw,
                          const float* __restrict__ cb,
                          float* __restrict__ h_in)
{
    int idx = blockIdx.x * blockDim.x + threadIdx.x;
    int b = idx >> 9, n = idx & 511;
    const float* xr = x + (size_t)b * (D_IN + D_COND) + D_IN;
    h_in[(size_t)b * HID + LPN + n] =
        cb[n] + xr[0]*cw[n*3+0] + xr[1]*cw[n*3+1] + xr[2]*cw[n*3+2];
}

__device__ __forceinline__ float sigm(float v) { return 1.f / (1.f + expf(-v)); }

__global__ void gru_gate(const float* __restrict__ gi,
                         const float* __restrict__ gh,
                         const float* __restrict__ hprev,
                         float* __restrict__ hout,
                         float* __restrict__ dec_in, int writeDec)
{
    int idx = blockIdx.x * blockDim.x + threadIdx.x;
    int b = idx >> 10, j = idx & 1023;
    const float* gib = gi + (size_t)b * H3;
    const float* ghb = gh + (size_t)b * H3;
    float r = sigm(gib[j] + ghb[j]);
    float z = sigm(gib[HID + j] + ghb[HID + j]);
    float n = tanhf(gib[2*HID + j] + r * ghb[2*HID + j]);
    float hp = hprev[idx];
    float h = (1.f - z) * n + z * hp;
    hout[idx] = h;
    if (writeDec) dec_in[(size_t)b * DECK + j] = h;
}

__global__ void zero_tail(float* __restrict__ dec_in)
{
    int idx = blockIdx.x * blockDim.x + threadIdx.x;
    int b = idx >> 7, j = idx & 127;
    dec_in[(size_t)b * DECK + HID + j] = 0.f;
}

// E (NQ,K,D_IN) -> ET (NQ,D_IN,K)
__global__ void transposeE(const float* __restrict__ E, float* __restrict__ ET)
{
    __shared__ float t[32][33];
    int q = blockIdx.z;
    int k0 = blockIdx.x * 32, n0 = blockIdx.y * 32;
    const float* Eq = E + (size_t)q * KCB * D_IN;
    float* Tq = ET + (size_t)q * D_IN * KCB;
#pragma unroll
    for (int i = 0; i < 32; i += 8)
        t[threadIdx.y + i][threadIdx.x] =
            Eq[(size_t)(k0 + threadIdx.y + i) * D_IN + n0 + threadIdx.x];
    __syncthreads();
#pragma unroll
    for (int i = 0; i < 32; i += 8)
        Tq[(size_t)(n0 + threadIdx.y + i) * KCB + k0 + threadIdx.x] =
            t[threadIdx.x][threadIdx.y + i];
}

// normalized softmax(logits * inv_tau) -> w   (one warp per row)
__global__ void __launch_bounds__(256)
softmax_w(const float* __restrict__ logits, float* __restrict__ w)
{
    const int warp = threadIdx.x >> 5, lane = threadIdx.x & 31;
    const size_t row = (size_t)blockIdx.x * 8 + warp;
    const float* lr = logits + row * KCB;
    float v[32];
    float m = -INFINITY;
#pragma unroll
    for (int i = 0; i < 32; i++) { v[i] = lr[lane + 32*i]; m = fmaxf(m, v[i]); }
#pragma unroll
    for (int o = 16; o; o >>= 1) m = fmaxf(m, __shfl_xor_sync(0xffffffffu, m, o));
    float s = 0.f;
#pragma unroll
    for (int i = 0; i < 32; i++) { v[i] = expf((v[i] - m) * INV_TAU); s += v[i]; }
#pragma unroll
    for (int o = 16; o; o >>= 1) s += __shfl_xor_sync(0xffffffffu, s, o);
    float inv = 1.f / s;
    float* wr = w + row * KCB;
#pragma unroll
    for (int i = 0; i < 32; i++) wr[lane + 32*i] = v[i] * inv;
}

// cum += e (if q<NQ-1); step accumulate (write at q==0 since d_out poisoned)
__global__ void rvq_update(const float* __restrict__ e,
                           float* __restrict__ dec_in,
                           float* __restrict__ step_out, int q)
{
    int idx = blockIdx.x * blockDim.x + threadIdx.x;
    int b = idx >> 7, j = idx & 127;
    float v = e[idx];
    float prev = (q == 0) ? 0.f : step_out[idx];
    step_out[idx] = prev + v;
    if (q < NQ - 1) dec_in[(size_t)b * DECK + HID + j] += v;
}

// =====================================================================
extern "C" void kernel_launch(void* const* d_in, const int* in_sizes, int n_in,
                              void* d_out, int out_size)
{
    const float* x      = (const float*)d_in[0];
    const float* hidden = (const float*)d_in[1];
    const float* lat_w  = (const float*)d_in[2];
    const float* lat_b  = (const float*)d_in[3];
    const float* cond_w = (const float*)d_in[4];
    const float* cond_b = (const float*)d_in[5];
    const float* gwih   = (const float*)d_in[6];
    const float* gwhh   = (const float*)d_in[7];
    const float* gbih   = (const float*)d_in[8];
    const float* gbhh   = (const float*)d_in[9];
    const float* dec_w  = (const float*)d_in[10];
    const float* dec_b  = (const float*)d_in[11];
    const float* E_eff  = (const float*)d_in[12];

    const size_t BH = (size_t)BATCH * HID;
    const size_t BK = (size_t)BATCH * KCB;

    float* out_logits = (float*)d_out;
    float* out_hidden = out_logits + (size_t)NQ * BK;
    float* out_step   = out_hidden + (size_t)NLAY * BH;

    float *h_in, *gi, *gh, *dec_in, *w, *e, *ET, *zerob;
    cudaGetSymbolAddress((void**)&h_in,   g_h_in);
    cudaGetSymbolAddress((void**)&gi,     g_gi);
    cudaGetSymbolAddress((void**)&gh,     g_gh);
    cudaGetSymbolAddress((void**)&dec_in, g_dec_in);
    cudaGetSymbolAddress((void**)&w,      g_w);
    cudaGetSymbolAddress((void**)&e,      g_e);
    cudaGetSymbolAddress((void**)&ET,     g_ET);
    cudaGetSymbolAddress((void**)&zerob,  g_zero);

    const int SMEM = 4 * STAGE_F * 4;   // 2 stages x (A+B) x 128x36 floats = 73728 B
    cudaFuncSetAttribute(mma_gemm, cudaFuncAttributeMaxDynamicSharedMemorySize, SMEM);

    // ---- input projections ----
    sgemm_lat<<<dim3(LPN/128, BATCH/128), 256>>>(
        x, D_IN + D_COND, lat_w, D_IN, lat_b, h_in, HID, D_IN);
    cond_proj<<<(BATCH*512)/256, 256>>>(x, cond_w, cond_b, h_in);

    // ---- E transpose (independent; needed before q-loop) ----
    transposeE<<<dim3(KCB/32, D_IN/32, NQ), dim3(32, 8)>>>(E_eff, ET);

    // ---- 4-layer GRU ----
    for (int l = 0; l < NLAY; l++) {
        const float* xl = (l == 0) ? h_in : (out_hidden + (size_t)(l-1) * BH);
        mma_gemm<<<dim3(H3/128, BATCH/128), 256, SMEM>>>(
            xl, HID, gwih + (size_t)l * H3 * HID, HID,
            gbih + (size_t)l * H3, gi, H3, HID);
        mma_gemm<<<dim3(H3/128, BATCH/128), 256, SMEM>>>(
            hidden + (size_t)l * BH, HID, gwhh + (size_t)l * H3 * HID, HID,
            gbhh + (size_t)l * H3, gh, H3, HID);
        gru_gate<<<(int)(BH/256), 256>>>(
            gi, gh, hidden + (size_t)l * BH,
            out_hidden + (size_t)l * BH, dec_in, (l == NLAY-1) ? 1 : 0);
    }

    // ---- RVQ cascade ----
    zero_tail<<<(BATCH*D_IN)/256, 256>>>(dec_in);
    for (int q = 0; q < NQ; q++) {
        mma_gemm<<<dim3(KCB/128, BATCH/128), 256, SMEM>>>(
            dec_in, DECK, dec_w + (size_t)q * KCB * DECK, DECK,
            dec_b + (size_t)q * KCB, out_logits + (size_t)q * BK, KCB, DECK);
        softmax_w<<<BATCH/8, 256>>>(out_logits + (size_t)q * BK, w);
        mma_gemm<<<dim3(1, BATCH/128), 256, SMEM>>>(
            w, KCB, ET + (size_t)q * D_IN * KCB, KCB,
            zerob, e, D_IN, KCB);
        rvq_update<<<(BATCH*D_IN)/256, 256>>>(e, dec_in, out_step, q);
    }
}

// round 5
// speedup vs baseline: 3.6658x; 1.0843x over previous
#include <cuda_runtime.h>
#include <cuda_bf16.h>
#include <math.h>
#include <stdint.h>

// ---------------- problem constants ----------------
#define BATCH   8192
#define D_IN    128
#define D_COND  3
#define HID     1024
#define NLAY    4
#define NQ      8
#define KCB     1024
#define H3      (3*HID)        // 3072
#define DECK    (HID + D_IN)   // 1152
#define LPN     512
#define INV_TAU (1.0f/0.6f)

// ---------------- scratch (no allocation allowed) ----------------
__device__ float g_h_in  [(size_t)BATCH * HID];
__device__ float g_gi    [(size_t)BATCH * H3];
__device__ float g_gh    [(size_t)BATCH * H3];
__device__ float g_dec_in[(size_t)BATCH * DECK];
__device__ float g_w     [(size_t)BATCH * KCB];     // softmax weights
__device__ float g_e     [(size_t)BATCH * D_IN];    // e_q
__device__ float g_ET    [(size_t)NQ * D_IN * KCB]; // E transposed
__device__ float g_zero  [1024];                    // stays 0 (never written)

// =====================================================================
// tf32 mma.sync GEMM:  C[M,N] = A[M,K] @ W[N,K]^T + bias[N]
//   BM=128, BN template (128/256), BK=32, 256 threads (8 warps, 2m x BN/64 n... 2x4),
//   warp tile 64 x (BN/4). cp.async double buffer.
//   Logical-k pairing: logical k=c and k=c+4 of each m16n8k8 step live at
//   physically adjacent smem columns (2c, 2c+1) for BOTH A and B, so fragment
//   loads are single LDS.64. Exact (k-sum is order invariant).
//   Requires: lda/ldw % 4 == 0, K % 32 == 0, M % 128 == 0, N % BN == 0.
// =====================================================================
#define SPAD 40                          // padded row stride (floats)

__device__ __forceinline__ uint32_t f2tf32(float f) {
    uint32_t u;
    asm("cvt.rna.tf32.f32 %0, %1;" : "=r"(u) : "f"(f));
    return u;
}

__device__ __forceinline__ void mma_tf32(float* c, const uint32_t* a, const uint32_t* b) {
    asm volatile(
        "mma.sync.aligned.m16n8k8.row.col.f32.tf32.tf32.f32 "
        "{%0,%1,%2,%3}, {%4,%5,%6,%7}, {%8,%9}, {%0,%1,%2,%3};"
        : "+f"(c[0]), "+f"(c[1]), "+f"(c[2]), "+f"(c[3])
        : "r"(a[0]), "r"(a[1]), "r"(a[2]), "r"(a[3]), "r"(b[0]), "r"(b[1]));
}

__device__ __forceinline__ uint32_t smem_u32(const void* p) {
    uint32_t a;
    asm("{ .reg .u64 t; cvta.to.shared.u64 t, %1; cvt.u32.u64 %0, t; }" : "=r"(a) : "l"(p));
    return a;
}
#define CP_ASYNC16(dst, src) \
    asm volatile("cp.async.cg.shared.global [%0], [%1], 16;" :: "r"(dst), "l"(src) : "memory")
#define CP_COMMIT() asm volatile("cp.async.commit_group;" ::: "memory")
template <int N> __device__ __forceinline__ void cp_wait() {
    asm volatile("cp.async.wait_group %0;" :: "n"(N) : "memory");
}

template <int BN>
__global__ void __launch_bounds__(256, 1)
mma_gemm(const float* __restrict__ A, int lda,
         const float* __restrict__ W, int ldw,
         const float* __restrict__ bias,
         float* __restrict__ C, int ldc, int K)
{
    constexpr int NT = BN / 32;              // b-frag tiles per warp (n dir)
    constexpr int ASTG = 128 * SPAD;         // A floats per stage
    constexpr int BSTG = BN * SPAD;          // B floats per stage

    extern __shared__ float smem[];
    float* As = smem;                        // [2][128][SPAD]
    float* Bs = smem + 2 * ASTG;             // [2][BN][SPAD]

    const int tid  = threadIdx.x;
    const int lane = tid & 31, wid = tid >> 5;
    const int bm = blockIdx.y * 128, bn = blockIdx.x * BN;
    const int wm = (wid >> 2) << 6;          // 0 / 64
    const int wn = (wid & 3) * (BN / 4);

    const int lrow = tid >> 3;               // 0..31
    const int lq   = tid & 7;                // float4 index in 32-float row
    const uint32_t sA = smem_u32(As);
    const uint32_t sB = smem_u32(Bs);

    float acc[4][NT][4];
#pragma unroll
    for (int i = 0; i < 4; i++)
#pragma unroll
        for (int j = 0; j < NT; j++)
#pragma unroll
            for (int k = 0; k < 4; k++) acc[i][j][k] = 0.f;

    const int nK = K / 32;

    auto prefetch = [&](int kt, int s) {
        const float* Ab = A + (size_t)(bm + lrow) * lda + kt * 32 + lq * 4;
        uint32_t dA = sA + (s * ASTG + lrow * SPAD + lq * 4) * 4;
#pragma unroll
        for (int i = 0; i < 4; i++)
            CP_ASYNC16(dA + i * 32 * SPAD * 4, Ab + (size_t)(i * 32) * lda);
        const float* Wb = W + (size_t)(bn + lrow) * ldw + kt * 32 + lq * 4;
        uint32_t dB = sB + (s * BSTG + lrow * SPAD + lq * 4) * 4;
#pragma unroll
        for (int i = 0; i < BN / 32; i++)
            CP_ASYNC16(dB + i * 32 * SPAD * 4, Wb + (size_t)(i * 32) * ldw);
        CP_COMMIT();
    };

    prefetch(0, 0);

    for (int kt = 0; kt < nK; kt++) {
        if (kt + 1 < nK) {
            prefetch(kt + 1, (kt + 1) & 1);
            cp_wait<1>();
        } else {
            cp_wait<0>();
        }
        __syncthreads();

        const float* Ac = As + (kt & 1) * ASTG;
        const float* Bc = Bs + (kt & 1) * BSTG;
#pragma unroll
        for (int k8 = 0; k8 < 4; k8++) {
            const int kb = k8 * 8 + 2 * (lane & 3);   // physical col pair base
            uint32_t a[4][4], b[NT][2];
#pragma unroll
            for (int mt = 0; mt < 4; mt++) {
                const int r = wm + mt * 16 + (lane >> 2);
                float2 p0 = *(const float2*)(Ac + r * SPAD + kb);
                float2 p1 = *(const float2*)(Ac + (r + 8) * SPAD + kb);
                a[mt][0] = f2tf32(p0.x);
                a[mt][1] = f2tf32(p1.x);
                a[mt][2] = f2tf32(p0.y);
                a[mt][3] = f2tf32(p1.y);
            }
#pragma unroll
            for (int nt = 0; nt < NT; nt++) {
                const int r = wn + nt * 8 + (lane >> 2);
                float2 p = *(const float2*)(Bc + r * SPAD + kb);
                b[nt][0] = f2tf32(p.x);
                b[nt][1] = f2tf32(p.y);
            }
#pragma unroll
            for (int mt = 0; mt < 4; mt++)
#pragma unroll
                for (int nt = 0; nt < NT; nt++)
                    mma_tf32(acc[mt][nt], a[mt], b[nt]);
        }
        __syncthreads();
    }

    // ---- epilogue ----
#pragma unroll
    for (int mt = 0; mt < 4; mt++) {
        const int r0 = bm + wm + mt * 16 + (lane >> 2);
#pragma unroll
        for (int nt = 0; nt < NT; nt++) {
            const int c0 = bn + wn + nt * 8 + (lane & 3) * 2;
            const float b0 = bias[c0], b1 = bias[c0 + 1];
            float2 v0 = make_float2(acc[mt][nt][0] + b0, acc[mt][nt][1] + b1);
            float2 v1 = make_float2(acc[mt][nt][2] + b0, acc[mt][nt][3] + b1);
            *(float2*)(C + (size_t)r0 * ldc + c0) = v0;
            *(float2*)(C + (size_t)(r0 + 8) * ldc + c0) = v1;
        }
    }
}

// =====================================================================
// fp32 SGEMM kept only for the tiny latent projection (lda=131, unaligned)
// =====================================================================
__global__ void __launch_bounds__(256)
sgemm_lat(const float* __restrict__ A, int lda,
          const float* __restrict__ W, int ldw,
          const float* __restrict__ bias,
          float* __restrict__ C, int ldc, int K)
{
    __shared__ float As[8][128];
    __shared__ float Bs[8][128];
    const int tid = threadIdx.x;
    const int bm = blockIdx.y * 128, bn = blockIdx.x * 128;
    const int tRow = (tid >> 4) * 8, tCol = (tid & 15) * 8;
    const int lRow = tid >> 1, lCol = (tid & 1) * 4;
    const float* Aptr = A + (size_t)(bm + lRow) * lda + lCol;
    const float* Wptr = W + (size_t)(bn + lRow) * ldw + lCol;
    float acc[8][8];
#pragma unroll
    for (int i = 0; i < 8; i++)
#pragma unroll
        for (int j = 0; j < 8; j++) acc[i][j] = 0.f;
    for (int k0 = 0; k0 < K; k0 += 8) {
        float4 av;
        av.x = Aptr[k0]; av.y = Aptr[k0+1]; av.z = Aptr[k0+2]; av.w = Aptr[k0+3];
        float4 wv = *(const float4*)(Wptr + k0);
        As[lCol+0][lRow]=av.x; As[lCol+1][lRow]=av.y; As[lCol+2][lRow]=av.z; As[lCol+3][lRow]=av.w;
        Bs[lCol+0][lRow]=wv.x; Bs[lCol+1][lRow]=wv.y; Bs[lCol+2][lRow]=wv.z; Bs[lCol+3][lRow]=wv.w;
        __syncthreads();
#pragma unroll
        for (int kk = 0; kk < 8; kk++) {
            float ra[8], rb[8];
#pragma unroll
            for (int i = 0; i < 8; i++) ra[i] = As[kk][tRow+i];
#pragma unroll
            for (int j = 0; j < 8; j++) rb[j] = Bs[kk][tCol+j];
#pragma unroll
            for (int i = 0; i < 8; i++)
#pragma unroll
                for (int j = 0; j < 8; j++) acc[i][j] = fmaf(ra[i], rb[j], acc[i][j]);
        }
        __syncthreads();
    }
#pragma unroll
    for (int i = 0; i < 8; i++) {
        float* Crow = C + (size_t)(bm + tRow + i) * ldc + bn + tCol;
#pragma unroll
        for (int j = 0; j < 8; j++) Crow[j] = acc[i][j] + bias[bn + tCol + j];
    }
}

// =====================================================================
__global__ void cond_proj(const float* __restrict__ x,
                          const float* __restrict__ cw,
                          const float* __restrict__ cb,
                          float* __restrict__ h_in)
{
    int idx = blockIdx.x * blockDim.x + threadIdx.x;
    int b = idx >> 9, n = idx & 511;
    const float* xr = x + (size_t)b * (D_IN + D_COND) + D_IN;
    h_in[(size_t)b * HID + LPN + n] =
        cb[n] + xr[0]*cw[n*3+0] + xr[1]*cw[n*3+1] + xr[2]*cw[n*3+2];
}

__device__ __forceinline__ float sigm(float v) { return 1.f / (1.f + expf(-v)); }

// float4-vectorized GRU gates (torch r,z,n)
__global__ void gru_gate(const float* __restrict__ gi,
                         const float* __restrict__ gh,
                         const float* __restrict__ hprev,
                         float* __restrict__ hout,
                         float* __restrict__ dec_in, int writeDec)
{
    int idx = blockIdx.x * blockDim.x + threadIdx.x;   // BATCH * 256
    int b = idx >> 8, j4 = idx & 255;
    const float4* gib = (const float4*)(gi + (size_t)b * H3);
    const float4* ghb = (const float4*)(gh + (size_t)b * H3);
    float4 ir = gib[j4],       iz = gib[256 + j4], in4 = gib[512 + j4];
    float4 hr = ghb[j4],       hz = ghb[256 + j4], hn4 = ghb[512 + j4];
    float4 hp = ((const float4*)hprev)[idx];
    float4 h;
    {
        float r = sigm(ir.x + hr.x), z = sigm(iz.x + hz.x);
        float n = tanhf(in4.x + r * hn4.x); h.x = (1.f - z) * n + z * hp.x;
    }{
        float r = sigm(ir.y + hr.y), z = sigm(iz.y + hz.y);
        float n = tanhf(in4.y + r * hn4.y); h.y = (1.f - z) * n + z * hp.y;
    }{
        float r = sigm(ir.z + hr.z), z = sigm(iz.z + hz.z);
        float n = tanhf(in4.z + r * hn4.z); h.z = (1.f - z) * n + z * hp.z;
    }{
        float r = sigm(ir.w + hr.w), z = sigm(iz.w + hz.w);
        float n = tanhf(in4.w + r * hn4.w); h.w = (1.f - z) * n + z * hp.w;
    }
    ((float4*)hout)[idx] = h;
    if (writeDec) ((float4*)dec_in)[(size_t)b * (DECK/4) + j4] = h;
}

__global__ void zero_tail(float* __restrict__ dec_in)
{
    int idx = blockIdx.x * blockDim.x + threadIdx.x;   // BATCH * 32
    int b = idx >> 5, j4 = idx & 31;
    ((float4*)dec_in)[(size_t)b * (DECK/4) + 256 + j4] = make_float4(0.f,0.f,0.f,0.f);
}

// E (NQ,K,D_IN) -> ET (NQ,D_IN,K)
__global__ void transposeE(const float* __restrict__ E, float* __restrict__ ET)
{
    __shared__ float t[32][33];
    int q = blockIdx.z;
    int k0 = blockIdx.x * 32, n0 = blockIdx.y * 32;
    const float* Eq = E + (size_t)q * KCB * D_IN;
    float* Tq = ET + (size_t)q * D_IN * KCB;
#pragma unroll
    for (int i = 0; i < 32; i += 8)
        t[threadIdx.y + i][threadIdx.x] =
            Eq[(size_t)(k0 + threadIdx.y + i) * D_IN + n0 + threadIdx.x];
    __syncthreads();
#pragma unroll
    for (int i = 0; i < 32; i += 8)
        Tq[(size_t)(n0 + threadIdx.y + i) * KCB + k0 + threadIdx.x] =
            t[threadIdx.x][threadIdx.y + i];
}

// normalized softmax(logits * inv_tau) -> w   (one warp per row)
__global__ void __launch_bounds__(256)
softmax_w(const float* __restrict__ logits, float* __restrict__ w)
{
    const int warp = threadIdx.x >> 5, lane = threadIdx.x & 31;
    const size_t row = (size_t)blockIdx.x * 8 + warp;
    const float* lr = logits + row * KCB;
    float v[32];
    float m = -INFINITY;
#pragma unroll
    for (int i = 0; i < 32; i++) { v[i] = lr[lane + 32*i]; m = fmaxf(m, v[i]); }
#pragma unroll
    for (int o = 16; o; o >>= 1) m = fmaxf(m, __shfl_xor_sync(0xffffffffu, m, o));
    float s = 0.f;
#pragma unroll
    for (int i = 0; i < 32; i++) { v[i] = expf((v[i] - m) * INV_TAU); s += v[i]; }
#pragma unroll
    for (int o = 16; o; o >>= 1) s += __shfl_xor_sync(0xffffffffu, s, o);
    float inv = 1.f / s;
    float* wr = w + row * KCB;
#pragma unroll
    for (int i = 0; i < 32; i++) wr[lane + 32*i] = v[i] * inv;
}

// cum += e (if q<NQ-1); step accumulate (write at q==0 since d_out poisoned)
__global__ void rvq_update(const float* __restrict__ e,
                           float* __restrict__ dec_in,
                           float* __restrict__ step_out, int q)
{
    int idx = blockIdx.x * blockDim.x + threadIdx.x;   // BATCH * 32
    int b = idx >> 5, j4 = idx & 31;
    float4 v = ((const float4*)e)[idx];
    float4 prev = (q == 0) ? make_float4(0.f,0.f,0.f,0.f) : ((const float4*)step_out)[idx];
    prev.x += v.x; prev.y += v.y; prev.z += v.z; prev.w += v.w;
    ((float4*)step_out)[idx] = prev;
    if (q < NQ - 1) {
        float4* c = (float4*)dec_in + (size_t)b * (DECK/4) + 256 + j4;
        float4 cv = *c;
        cv.x += v.x; cv.y += v.y; cv.z += v.z; cv.w += v.w;
        *c = cv;
    }
}

// =====================================================================
extern "C" void kernel_launch(void* const* d_in, const int* in_sizes, int n_in,
                              void* d_out, int out_size)
{
    const float* x      = (const float*)d_in[0];
    const float* hidden = (const float*)d_in[1];
    const float* lat_w  = (const float*)d_in[2];
    const float* lat_b  = (const float*)d_in[3];
    const float* cond_w = (const float*)d_in[4];
    const float* cond_b = (const float*)d_in[5];
    const float* gwih   = (const float*)d_in[6];
    const float* gwhh   = (const float*)d_in[7];
    const float* gbih   = (const float*)d_in[8];
    const float* gbhh   = (const float*)d_in[9];
    const float* dec_w  = (const float*)d_in[10];
    const float* dec_b  = (const float*)d_in[11];
    const float* E_eff  = (const float*)d_in[12];

    const size_t BH = (size_t)BATCH * HID;
    const size_t BK = (size_t)BATCH * KCB;

    float* out_logits = (float*)d_out;
    float* out_hidden = out_logits + (size_t)NQ * BK;
    float* out_step   = out_hidden + (size_t)NLAY * BH;

    float *h_in, *gi, *gh, *dec_in, *w, *e, *ET, *zerob;
    cudaGetSymbolAddress((void**)&h_in,   g_h_in);
    cudaGetSymbolAddress((void**)&gi,     g_gi);
    cudaGetSymbolAddress((void**)&gh,     g_gh);
    cudaGetSymbolAddress((void**)&dec_in, g_dec_in);
    cudaGetSymbolAddress((void**)&w,      g_w);
    cudaGetSymbolAddress((void**)&e,      g_e);
    cudaGetSymbolAddress((void**)&ET,     g_ET);
    cudaGetSymbolAddress((void**)&zerob,  g_zero);

    const int SM256 = 2 * (128 + 256) * SPAD * 4;   // 122880 B
    const int SM128 = 2 * (128 + 128) * SPAD * 4;   // 81920 B
    cudaFuncSetAttribute(mma_gemm<256>, cudaFuncAttributeMaxDynamicSharedMemorySize, SM256);
    cudaFuncSetAttribute(mma_gemm<128>, cudaFuncAttributeMaxDynamicSharedMemorySize, SM128);

    // ---- input projections ----
    sgemm_lat<<<dim3(LPN/128, BATCH/128), 256>>>(
        x, D_IN + D_COND, lat_w, D_IN, lat_b, h_in, HID, D_IN);
    cond_proj<<<(BATCH*512)/256, 256>>>(x, cond_w, cond_b, h_in);

    // ---- E transpose (independent; needed before q-loop) ----
    transposeE<<<dim3(KCB/32, D_IN/32, NQ), dim3(32, 8)>>>(E_eff, ET);

    // ---- 4-layer GRU ----
    for (int l = 0; l < NLAY; l++) {
        const float* xl = (l == 0) ? h_in : (out_hidden + (size_t)(l-1) * BH);
        mma_gemm<256><<<dim3(H3/256, BATCH/128), 256, SM256>>>(
            xl, HID, gwih + (size_t)l * H3 * HID, HID,
            gbih + (size_t)l * H3, gi, H3, HID);
        mma_gemm<256><<<dim3(H3/256, BATCH/128), 256, SM256>>>(
            hidden + (size_t)l * BH, HID, gwhh + (size_t)l * H3 * HID, HID,
            gbhh + (size_t)l * H3, gh, H3, HID);
        gru_gate<<<(int)(BH/4/256), 256>>>(
            gi, gh, hidden + (size_t)l * BH,
            out_hidden + (size_t)l * BH, dec_in, (l == NLAY-1) ? 1 : 0);
    }

    // ---- RVQ cascade ----
    zero_tail<<<(BATCH*32)/256, 256>>>(dec_in);
    for (int q = 0; q < NQ; q++) {
        mma_gemm<256><<<dim3(KCB/256, BATCH/128), 256, SM256>>>(
            dec_in, DECK, dec_w + (size_t)q * KCB * DECK, DECK,
            dec_b + (size_t)q * KCB, out_logits + (size_t)q * BK, KCB, DECK);
        softmax_w<<<BATCH/8, 256>>>(out_logits + (size_t)q * BK, w);
        mma_gemm<128><<<dim3(1, BATCH/128), 256, SM128>>>(
            w, KCB, ET + (size_t)q * D_IN * KCB, KCB,
            zerob, e, D_IN, KCB);
        rvq_update<<<(BATCH*32)/256, 256>>>(e, dec_in, out_step, q);
    }
}

// round 6
// speedup vs baseline: 3.8763x; 1.0574x over previous
#include <cuda_runtime.h>
#include <cuda_bf16.h>
#include <math.h>
#include <stdint.h>

// ---------------- problem constants ----------------
#define BATCH   8192
#define D_IN    128
#define D_COND  3
#define HID     1024
#define NLAY    4
#define NQ      8
#define KCB     1024
#define H3      (3*HID)        // 3072
#define DECK    (HID + D_IN)   // 1152
#define LPN     512
#define INV_TAU (1.0f/0.6f)

// ---------------- scratch (no allocation allowed) ----------------
__device__ float    g_gi   [(size_t)BATCH * H3];
__device__ float    g_gh   [(size_t)BATCH * H3];
__device__ float    g_e    [(size_t)BATCH * D_IN];     // e_q (fp32 GEMM out)
__device__ float    g_cum  [(size_t)BATCH * D_IN];     // fp32 running cum
__device__ float    g_zero [1024];                     // stays 0
// tf32-bit operand copies (uint32)
__device__ uint32_t g_xl_t [(size_t)BATCH * HID];      // current layer input
__device__ uint32_t g_hid_t[(size_t)NLAY * BATCH * HID];
__device__ uint32_t g_wih_t[(size_t)NLAY * H3 * HID];
__device__ uint32_t g_whh_t[(size_t)NLAY * H3 * HID];
__device__ uint32_t g_dw_t [(size_t)NQ * KCB * DECK];
__device__ uint32_t g_ET_t [(size_t)NQ * D_IN * KCB];
__device__ uint32_t g_dec_t[(size_t)BATCH * DECK];     // [h_out | cum] tf32
__device__ uint32_t g_w_t  [(size_t)BATCH * KCB];      // softmax weights tf32

// =====================================================================
#define SPAD 40                          // padded row stride (words)

__device__ __forceinline__ uint32_t f2tf32(float f) {
    uint32_t u;
    asm("cvt.rna.tf32.f32 %0, %1;" : "=r"(u) : "f"(f));
    return u;
}

__device__ __forceinline__ void mma_tf32(float* c, const uint32_t* a, const uint32_t* b) {
    asm volatile(
        "mma.sync.aligned.m16n8k8.row.col.f32.tf32.tf32.f32 "
        "{%0,%1,%2,%3}, {%4,%5,%6,%7}, {%8,%9}, {%0,%1,%2,%3};"
        : "+f"(c[0]), "+f"(c[1]), "+f"(c[2]), "+f"(c[3])
        : "r"(a[0]), "r"(a[1]), "r"(a[2]), "r"(a[3]), "r"(b[0]), "r"(b[1]));
}

__device__ __forceinline__ uint32_t smem_u32(const void* p) {
    uint32_t a;
    asm("{ .reg .u64 t; cvta.to.shared.u64 t, %1; cvt.u32.u64 %0, t; }" : "=r"(a) : "l"(p));
    return a;
}
#define CP_ASYNC16(dst, src) \
    asm volatile("cp.async.cg.shared.global [%0], [%1], 16;" :: "r"(dst), "l"(src) : "memory")
#define CP_COMMIT() asm volatile("cp.async.commit_group;" ::: "memory")
template <int N> __device__ __forceinline__ void cp_wait() {
    asm volatile("cp.async.wait_group %0;" :: "n"(N) : "memory");
}

// =====================================================================
// tf32 mma.sync GEMM on pre-converted operands:
//   C[M,N] = A_t[M,K] @ W_t[N,K]^T + bias[N]   (A_t, W_t already tf32 bits)
//   BM=128, BN template, BK=32, 256 threads (2m x 4n warps),
//   warp tile 64 x BN/4, 3-stage cp.async pipeline, ONE sync per k-tile.
//   Logical-k pairing -> all fragment loads are LDS.64; zero inner-loop CVT.
// =====================================================================
template <int BN>
__global__ void __launch_bounds__(256, 1)
mma_gemm(const uint32_t* __restrict__ A, int lda,
         const uint32_t* __restrict__ W, int ldw,
         const float* __restrict__ bias,
         float* __restrict__ C, int ldc, int K)
{
    constexpr int NT   = BN / 32;
    constexpr int ASTG = 128 * SPAD;
    constexpr int BSTG = BN * SPAD;
    constexpr int STG  = ASTG + BSTG;

    extern __shared__ uint32_t smem[];   // [3][A:128][SPAD] + [3][B:BN][SPAD] interleaved per stage

    const int tid  = threadIdx.x;
    const int lane = tid & 31, wid = tid >> 5;
    const int bm = blockIdx.y * 128, bn = blockIdx.x * BN;
    const int wm = (wid >> 2) << 6;
    const int wn = (wid & 3) * (BN / 4);

    const int lrow = tid >> 3;               // 0..31
    const int lq   = tid & 7;
    const uint32_t sBase = smem_u32(smem);

    float acc[4][NT][4];
#pragma unroll
    for (int i = 0; i < 4; i++)
#pragma unroll
        for (int j = 0; j < NT; j++)
#pragma unroll
            for (int k = 0; k < 4; k++) acc[i][j][k] = 0.f;

    const int nK = K / 32;

    auto prefetch = [&](int kt) {
        const int s = kt % 3;
        const uint32_t* Ab = A + (size_t)(bm + lrow) * lda + kt * 32 + lq * 4;
        uint32_t dA = sBase + (s * STG + lrow * SPAD + lq * 4) * 4;
#pragma unroll
        for (int i = 0; i < 4; i++)
            CP_ASYNC16(dA + i * 32 * SPAD * 4, Ab + (size_t)(i * 32) * lda);
        const uint32_t* Wb = W + (size_t)(bn + lrow) * ldw + kt * 32 + lq * 4;
        uint32_t dB = sBase + (s * STG + ASTG + lrow * SPAD + lq * 4) * 4;
#pragma unroll
        for (int i = 0; i < BN / 32; i++)
            CP_ASYNC16(dB + i * 32 * SPAD * 4, Wb + (size_t)(i * 32) * ldw);
        CP_COMMIT();
    };

    prefetch(0);
    if (nK > 1) prefetch(1);

    for (int kt = 0; kt < nK; kt++) {
        if (kt + 1 < nK) cp_wait<1>(); else cp_wait<0>();
        __syncthreads();
        if (kt + 2 < nK) prefetch(kt + 2);   // writes stage (kt-1)%3: safe past barrier

        const uint32_t* Ac = smem + (kt % 3) * STG;
        const uint32_t* Bc = Ac + ASTG;
#pragma unroll
        for (int k8 = 0; k8 < 4; k8++) {
            const int kb = k8 * 8 + 2 * (lane & 3);
            uint32_t a[4][4], b[NT][2];
#pragma unroll
            for (int mt = 0; mt < 4; mt++) {
                const int r = wm + mt * 16 + (lane >> 2);
                uint2 p0 = *(const uint2*)(Ac + r * SPAD + kb);
                uint2 p1 = *(const uint2*)(Ac + (r + 8) * SPAD + kb);
                a[mt][0] = p0.x; a[mt][1] = p1.x; a[mt][2] = p0.y; a[mt][3] = p1.y;
            }
#pragma unroll
            for (int nt = 0; nt < NT; nt++) {
                const int r = wn + nt * 8 + (lane >> 2);
                uint2 p = *(const uint2*)(Bc + r * SPAD + kb);
                b[nt][0] = p.x; b[nt][1] = p.y;
            }
#pragma unroll
            for (int mt = 0; mt < 4; mt++)
#pragma unroll
                for (int nt = 0; nt < NT; nt++)
                    mma_tf32(acc[mt][nt], a[mt], b[nt]);
        }
    }

#pragma unroll
    for (int mt = 0; mt < 4; mt++) {
        const int r0 = bm + wm + mt * 16 + (lane >> 2);
#pragma unroll
        for (int nt = 0; nt < NT; nt++) {
            const int c0 = bn + wn + nt * 8 + (lane & 3) * 2;
            const float b0 = bias[c0], b1 = bias[c0 + 1];
            float2 v0 = make_float2(acc[mt][nt][0] + b0, acc[mt][nt][1] + b1);
            float2 v1 = make_float2(acc[mt][nt][2] + b0, acc[mt][nt][3] + b1);
            *(float2*)(C + (size_t)r0 * ldc + c0) = v0;
            *(float2*)(C + (size_t)(r0 + 8) * ldc + c0) = v1;
        }
    }
}

// =====================================================================
// fp32 -> tf32-bits bulk convert (vec4)
// =====================================================================
__global__ void conv_tf32(const float4* __restrict__ src, uint4* __restrict__ dst, int n4)
{
    int i = blockIdx.x * blockDim.x + threadIdx.x;
    if (i >= n4) return;
    float4 v = src[i];
    uint4 u;
    u.x = f2tf32(v.x); u.y = f2tf32(v.y); u.z = f2tf32(v.z); u.w = f2tf32(v.w);
    dst[i] = u;
}

// =====================================================================
// latent projection -> tf32 bits into xl_t[:, 0:512]  (lda=131, unaligned)
// =====================================================================
__global__ void __launch_bounds__(256)
sgemm_lat(const float* __restrict__ A, int lda,
          const float* __restrict__ W, int ldw,
          const float* __restrict__ bias,
          uint32_t* __restrict__ C, int ldc, int K)
{
    __shared__ float As[8][128];
    __shared__ float Bs[8][128];
    const int tid = threadIdx.x;
    const int bm = blockIdx.y * 128, bn = blockIdx.x * 128;
    const int tRow = (tid >> 4) * 8, tCol = (tid & 15) * 8;
    const int lRow = tid >> 1, lCol = (tid & 1) * 4;
    const float* Aptr = A + (size_t)(bm + lRow) * lda + lCol;
    const float* Wptr = W + (size_t)(bn + lRow) * ldw + lCol;
    float acc[8][8];
#pragma unroll
    for (int i = 0; i < 8; i++)
#pragma unroll
        for (int j = 0; j < 8; j++) acc[i][j] = 0.f;
    for (int k0 = 0; k0 < K; k0 += 8) {
        float4 av;
        av.x = Aptr[k0]; av.y = Aptr[k0+1]; av.z = Aptr[k0+2]; av.w = Aptr[k0+3];
        float4 wv = *(const float4*)(Wptr + k0);
        As[lCol+0][lRow]=av.x; As[lCol+1][lRow]=av.y; As[lCol+2][lRow]=av.z; As[lCol+3][lRow]=av.w;
        Bs[lCol+0][lRow]=wv.x; Bs[lCol+1][lRow]=wv.y; Bs[lCol+2][lRow]=wv.z; Bs[lCol+3][lRow]=wv.w;
        __syncthreads();
#pragma unroll
        for (int kk = 0; kk < 8; kk++) {
            float ra[8], rb[8];
#pragma unroll
            for (int i = 0; i < 8; i++) ra[i] = As[kk][tRow+i];
#pragma unroll
            for (int j = 0; j < 8; j++) rb[j] = Bs[kk][tCol+j];
#pragma unroll
            for (int i = 0; i < 8; i++)
#pragma unroll
                for (int j = 0; j < 8; j++) acc[i][j] = fmaf(ra[i], rb[j], acc[i][j]);
        }
        __syncthreads();
    }
#pragma unroll
    for (int i = 0; i < 8; i++) {
        uint32_t* Crow = C + (size_t)(bm + tRow + i) * ldc + bn + tCol;
#pragma unroll
        for (int j = 0; j < 8; j++) Crow[j] = f2tf32(acc[i][j] + bias[bn + tCol + j]);
    }
}

// cond projection -> tf32 bits into xl_t[:, 512:1024]
__global__ void cond_proj(const float* __restrict__ x,
                          const float* __restrict__ cw,
                          const float* __restrict__ cb,
                          uint32_t* __restrict__ xl_t)
{
    int idx = blockIdx.x * blockDim.x + threadIdx.x;
    int b = idx >> 9, n = idx & 511;
    const float* xr = x + (size_t)b * (D_IN + D_COND) + D_IN;
    float v = cb[n] + xr[0]*cw[n*3+0] + xr[1]*cw[n*3+1] + xr[2]*cw[n*3+2];
    xl_t[(size_t)b * HID + LPN + n] = f2tf32(v);
}

__device__ __forceinline__ float sigm(float v) { return 1.f / (1.f + expf(-v)); }

// GRU gates: writes fp32 h (output), tf32 h (next-layer A operand), dec head
__global__ void gru_gate(const float* __restrict__ gi,
                         const float* __restrict__ gh,
                         const float* __restrict__ hprev,
                         float* __restrict__ hout,
                         uint32_t* __restrict__ xl_t,
                         uint32_t* __restrict__ dec_t, int writeDec)
{
    int idx = blockIdx.x * blockDim.x + threadIdx.x;   // BATCH * 256
    int b = idx >> 8, j4 = idx & 255;
    const float4* gib = (const float4*)(gi + (size_t)b * H3);
    const float4* ghb = (const float4*)(gh + (size_t)b * H3);
    float4 ir = gib[j4], iz = gib[256 + j4], in4 = gib[512 + j4];
    float4 hr = ghb[j4], hz = ghb[256 + j4], hn4 = ghb[512 + j4];
    float4 hp = ((const float4*)hprev)[idx];
    float4 h;
    {
        float r = sigm(ir.x + hr.x), z = sigm(iz.x + hz.x);
        float n = tanhf(in4.x + r * hn4.x); h.x = (1.f - z) * n + z * hp.x;
    }{
        float r = sigm(ir.y + hr.y), z = sigm(iz.y + hz.y);
        float n = tanhf(in4.y + r * hn4.y); h.y = (1.f - z) * n + z * hp.y;
    }{
        float r = sigm(ir.z + hr.z), z = sigm(iz.z + hz.z);
        float n = tanhf(in4.z + r * hn4.z); h.z = (1.f - z) * n + z * hp.z;
    }{
        float r = sigm(ir.w + hr.w), z = sigm(iz.w + hz.w);
        float n = tanhf(in4.w + r * hn4.w); h.w = (1.f - z) * n + z * hp.w;
    }
    ((float4*)hout)[idx] = h;
    uint4 ht;
    ht.x = f2tf32(h.x); ht.y = f2tf32(h.y); ht.z = f2tf32(h.z); ht.w = f2tf32(h.w);
    ((uint4*)xl_t)[idx] = ht;
    if (writeDec) ((uint4*)dec_t)[(size_t)b * (DECK/4) + j4] = ht;
}

__global__ void zero_tail(uint32_t* __restrict__ dec_t)
{
    int idx = blockIdx.x * blockDim.x + threadIdx.x;   // BATCH * 32
    int b = idx >> 5, j4 = idx & 31;
    ((uint4*)dec_t)[(size_t)b * (DECK/4) + 256 + j4] = make_uint4(0,0,0,0);
}

// E (NQ,K,D_IN) -> ET_t (NQ,D_IN,K) tf32 bits
__global__ void transposeE(const float* __restrict__ E, uint32_t* __restrict__ ET)
{
    __shared__ float t[32][33];
    int q = blockIdx.z;
    int k0 = blockIdx.x * 32, n0 = blockIdx.y * 32;
    const float* Eq = E + (size_t)q * KCB * D_IN;
    uint32_t* Tq = ET + (size_t)q * D_IN * KCB;
#pragma unroll
    for (int i = 0; i < 32; i += 8)
        t[threadIdx.y + i][threadIdx.x] =
            Eq[(size_t)(k0 + threadIdx.y + i) * D_IN + n0 + threadIdx.x];
    __syncthreads();
#pragma unroll
    for (int i = 0; i < 32; i += 8)
        Tq[(size_t)(n0 + threadIdx.y + i) * KCB + k0 + threadIdx.x] =
            f2tf32(t[threadIdx.x][threadIdx.y + i]);
}

// softmax(logits/tau) -> tf32 bits (one warp per row)
__global__ void __launch_bounds__(256)
softmax_w(const float* __restrict__ logits, uint32_t* __restrict__ w_t)
{
    const int warp = threadIdx.x >> 5, lane = threadIdx.x & 31;
    const size_t row = (size_t)blockIdx.x * 8 + warp;
    const float* lr = logits + row * KCB;
    float v[32];
    float m = -INFINITY;
#pragma unroll
    for (int i = 0; i < 32; i++) { v[i] = lr[lane + 32*i]; m = fmaxf(m, v[i]); }
#pragma unroll
    for (int o = 16; o; o >>= 1) m = fmaxf(m, __shfl_xor_sync(0xffffffffu, m, o));
    float s = 0.f;
#pragma unroll
    for (int i = 0; i < 32; i++) { v[i] = expf((v[i] - m) * INV_TAU); s += v[i]; }
#pragma unroll
    for (int o = 16; o; o >>= 1) s += __shfl_xor_sync(0xffffffffu, s, o);
    float inv = 1.f / s;
    uint32_t* wr = w_t + row * KCB;
#pragma unroll
    for (int i = 0; i < 32; i++) wr[lane + 32*i] = f2tf32(v[i] * inv);
}

// cum += e (fp32 master), write tf32 cum into dec tail; accumulate step
__global__ void rvq_update(const float* __restrict__ e,
                           float* __restrict__ cum,
                           uint32_t* __restrict__ dec_t,
                           float* __restrict__ step_out, int q)
{
    int idx = blockIdx.x * blockDim.x + threadIdx.x;   // BATCH * 32
    int b = idx >> 5, j4 = idx & 31;
    float4 v = ((const float4*)e)[idx];
    float4 prev = (q == 0) ? make_float4(0.f,0.f,0.f,0.f) : ((const float4*)step_out)[idx];
    prev.x += v.x; prev.y += v.y; prev.z += v.z; prev.w += v.w;
    ((float4*)step_out)[idx] = prev;
    if (q < NQ - 1) {
        float4 c = (q == 0) ? make_float4(0.f,0.f,0.f,0.f) : ((const float4*)cum)[idx];
        c.x += v.x; c.y += v.y; c.z += v.z; c.w += v.w;
        ((float4*)cum)[idx] = c;
        uint4 ct;
        ct.x = f2tf32(c.x); ct.y = f2tf32(c.y); ct.z = f2tf32(c.z); ct.w = f2tf32(c.w);
        ((uint4*)dec_t)[(size_t)b * (DECK/4) + 256 + j4] = ct;
    }
}

// =====================================================================
extern "C" void kernel_launch(void* const* d_in, const int* in_sizes, int n_in,
                              void* d_out, int out_size)
{
    const float* x      = (const float*)d_in[0];
    const float* hidden = (const float*)d_in[1];
    const float* lat_w  = (const float*)d_in[2];
    const float* lat_b  = (const float*)d_in[3];
    const float* cond_w = (const float*)d_in[4];
    const float* cond_b = (const float*)d_in[5];
    const float* gwih   = (const float*)d_in[6];
    const float* gwhh   = (const float*)d_in[7];
    const float* gbih   = (const float*)d_in[8];
    const float* gbhh   = (const float*)d_in[9];
    const float* dec_w  = (const float*)d_in[10];
    const float* dec_b  = (const float*)d_in[11];
    const float* E_eff  = (const float*)d_in[12];

    const size_t BH = (size_t)BATCH * HID;
    const size_t BK = (size_t)BATCH * KCB;

    float* out_logits = (float*)d_out;
    float* out_hidden = out_logits + (size_t)NQ * BK;
    float* out_step   = out_hidden + (size_t)NLAY * BH;

    float *gi, *gh, *e, *cum, *zerob;
    uint32_t *xl_t, *hid_t, *wih_t, *whh_t, *dw_t, *ET_t, *dec_t, *w_t;
    cudaGetSymbolAddress((void**)&gi,    g_gi);
    cudaGetSymbolAddress((void**)&gh,    g_gh);
    cudaGetSymbolAddress((void**)&e,     g_e);
    cudaGetSymbolAddress((void**)&cum,   g_cum);
    cudaGetSymbolAddress((void**)&zerob, g_zero);
    cudaGetSymbolAddress((void**)&xl_t,  g_xl_t);
    cudaGetSymbolAddress((void**)&hid_t, g_hid_t);
    cudaGetSymbolAddress((void**)&wih_t, g_wih_t);
    cudaGetSymbolAddress((void**)&whh_t, g_whh_t);
    cudaGetSymbolAddress((void**)&dw_t,  g_dw_t);
    cudaGetSymbolAddress((void**)&ET_t,  g_ET_t);
    cudaGetSymbolAddress((void**)&dec_t, g_dec_t);
    cudaGetSymbolAddress((void**)&w_t,   g_w_t);

    const int SM256 = 3 * (128 + 256) * SPAD * 4;   // 184320 B
    const int SM128 = 3 * (128 + 128) * SPAD * 4;   // 122880 B
    cudaFuncSetAttribute(mma_gemm<256>, cudaFuncAttributeMaxDynamicSharedMemorySize, SM256);
    cudaFuncSetAttribute(mma_gemm<128>, cudaFuncAttributeMaxDynamicSharedMemorySize, SM128);

    // ---- operand pre-conversion (weights + hidden) ----
    {
        int n4;
        n4 = (NLAY * H3 * HID) / 4;
        conv_tf32<<<(n4 + 255)/256, 256>>>((const float4*)gwih, (uint4*)wih_t, n4);
        conv_tf32<<<(n4 + 255)/256, 256>>>((const float4*)gwhh, (uint4*)whh_t, n4);
        n4 = (NQ * KCB * DECK) / 4;
        conv_tf32<<<(n4 + 255)/256, 256>>>((const float4*)dec_w, (uint4*)dw_t, n4);
        n4 = (int)((size_t)NLAY * BH / 4);
        conv_tf32<<<(n4 + 255)/256, 256>>>((const float4*)hidden, (uint4*)hid_t, n4);
    }

    // ---- input projections (write tf32 xl directly) ----
    sgemm_lat<<<dim3(LPN/128, BATCH/128), 256>>>(
        x, D_IN + D_COND, lat_w, D_IN, lat_b, xl_t, HID, D_IN);
    cond_proj<<<(BATCH*512)/256, 256>>>(x, cond_w, cond_b, xl_t);

    // ---- E transpose -> tf32 ----
    transposeE<<<dim3(KCB/32, D_IN/32, NQ), dim3(32, 8)>>>(E_eff, ET_t);

    // ---- 4-layer GRU ----
    for (int l = 0; l < NLAY; l++) {
        mma_gemm<256><<<dim3(H3/256, BATCH/128), 256, SM256>>>(
            xl_t, HID, wih_t + (size_t)l * H3 * HID, HID,
            gbih + (size_t)l * H3, gi, H3, HID);
        mma_gemm<256><<<dim3(H3/256, BATCH/128), 256, SM256>>>(
            hid_t + (size_t)l * BH, HID, whh_t + (size_t)l * H3 * HID, HID,
            gbhh + (size_t)l * H3, gh, H3, HID);
        gru_gate<<<(int)(BH/4/256), 256>>>(
            gi, gh, hidden + (size_t)l * BH,
            out_hidden + (size_t)l * BH, xl_t, dec_t, (l == NLAY-1) ? 1 : 0);
    }

    // ---- RVQ cascade ----
    zero_tail<<<(BATCH*32)/256, 256>>>(dec_t);
    for (int q = 0; q < NQ; q++) {
        mma_gemm<256><<<dim3(KCB/256, BATCH/128), 256, SM256>>>(
            dec_t, DECK, dw_t + (size_t)q * KCB * DECK, DECK,
            dec_b + (size_t)q * KCB, out_logits + (size_t)q * BK, KCB, DECK);
        softmax_w<<<BATCH/8, 256>>>(out_logits + (size_t)q * BK, w_t);
        mma_gemm<128><<<dim3(1, BATCH/128), 256, SM128>>>(
            w_t, KCB, ET_t + (size_t)q * D_IN * KCB, KCB,
            zerob, e, D_IN, KCB);
        rvq_update<<<(BATCH*32)/256, 256>>>(e, cum, dec_t, out_step, q);
    }
}